// round 1
// baseline (speedup 1.0000x reference)
#include <cuda_runtime.h>

// Problem shape (fixed by setup_inputs): B=32, S=2048, E=NQ=4.
#define NB 32
#define NS 2048
#define NE 4
#define NROWS (NB * NS)
#define QTILE 256
#define KCHUNK 1024

// Scratch (allocation-free rule: __device__ globals). 1 MB each.
__device__ float4 g_Qs[NROWS];  // Q pre-scaled by 0.5*log2(e)
__device__ float4 g_K[NROWS];
__device__ float4 g_V[NROWS];

// Collapsed quantum circuit: out_i are partial products of cos(x_q + w_q).
__device__ __forceinline__ float4 circuit4(float4 x, float w0, float w1, float w2, float w3) {
    float u0 = __cosf(x.x + w0);
    float u1 = __cosf(x.y + w1);
    float u2 = __cosf(x.z + w2);
    float u3 = __cosf(x.w + w3);
    float4 r;
    r.y = u0 * u1;          // <Z1> = c0 c1
    r.z = r.y * u2;         // <Z2> = c0 c1 c2
    r.w = r.z * u3;         // <Z3> = c0 c1 c2 c3
    r.x = u1 * u2 * u3;     // <Z0> = c1 c2 c3
    return r;
}

__global__ void __launch_bounds__(256) qkv_kernel(
    const float* __restrict__ x,
    const float* __restrict__ wQ,
    const float* __restrict__ wK,
    const float* __restrict__ wV)
{
    int n = blockIdx.x * blockDim.x + threadIdx.x;
    if (n >= NROWS) return;
    float4 xv = reinterpret_cast<const float4*>(x)[n];
    // Fold score scale (1/sqrt(E) = 0.5) and log2(e) (for ex2) into Q.
    const float ALPHA = 0.72134752044448170367f;  // 0.5 * log2(e)
    float4 q = circuit4(xv, wQ[0], wQ[1], wQ[2], wQ[3]);
    q.x *= ALPHA; q.y *= ALPHA; q.z *= ALPHA; q.w *= ALPHA;
    g_Qs[n] = q;
    g_K[n] = circuit4(xv, wK[0], wK[1], wK[2], wK[3]);
    g_V[n] = circuit4(xv, wV[0], wV[1], wV[2], wV[3]);
}

__global__ void __launch_bounds__(QTILE) attn_kernel(
    const float* __restrict__ wC, float* __restrict__ out)
{
    __shared__ float4 sK[KCHUNK];
    __shared__ float4 sV[KCHUNK];

    int b = blockIdx.y;
    int n = b * NS + blockIdx.x * QTILE + threadIdx.x;

    float4 q = g_Qs[n];
    float den = 0.f, a0 = 0.f, a1 = 0.f, a2 = 0.f, a3 = 0.f;

    for (int c0 = 0; c0 < NS; c0 += KCHUNK) {
        __syncthreads();
        for (int i = threadIdx.x; i < KCHUNK; i += QTILE) {
            sK[i] = g_K[b * NS + c0 + i];
            sV[i] = g_V[b * NS + c0 + i];
        }
        __syncthreads();
        #pragma unroll 8
        for (int j = 0; j < KCHUNK; j++) {
            float4 k = sK[j];   // warp-uniform index -> smem broadcast
            float4 v = sV[j];
            float s = q.x * k.x;
            s = fmaf(q.y, k.y, s);
            s = fmaf(q.z, k.z, s);
            s = fmaf(q.w, k.w, s);
            float w;
            asm("ex2.approx.f32 %0, %1;" : "=f"(w) : "f"(s));
            den += w;
            a0 = fmaf(w, v.x, a0);
            a1 = fmaf(w, v.y, a1);
            a2 = fmaf(w, v.z, a2);
            a3 = fmaf(w, v.w, a3);
        }
    }

    float inv = 1.0f / den;
    float4 ctx = make_float4(a0 * inv, a1 * inv, a2 * inv, a3 * inv);
    float4 o = circuit4(ctx, wC[0], wC[1], wC[2], wC[3]);
    reinterpret_cast<float4*>(out)[n] = o;
}

extern "C" void kernel_launch(void* const* d_in, const int* in_sizes, int n_in,
                              void* d_out, int out_size)
{
    const float* x  = (const float*)d_in[0];
    const float* wQ = (const float*)d_in[1];
    const float* wK = (const float*)d_in[2];
    const float* wV = (const float*)d_in[3];
    const float* wC = (const float*)d_in[4];
    float* out = (float*)d_out;

    qkv_kernel<<<NROWS / 256, 256>>>(x, wQ, wK, wV);

    dim3 grid(NS / QTILE, NB);
    attn_kernel<<<grid, QTILE>>>(wC, out);
}

// round 2
// speedup vs baseline: 1.0270x; 1.0270x over previous
#include <cuda_runtime.h>

// Shape fixed by setup_inputs: B=32, S=2048, E=NQ=4.
#define NB 32
#define NS 2048
#define NROWS (NB * NS)          // 65536 queries
#define NPAIRS (NROWS / 2)       // 32768 query pairs
#define KSPLIT 8
#define KEYS (NS / KSPLIT)       // 256 keys per split block
#define ATHREADS 128             // attn threads/block
#define QPT 8                    // queries per thread (4 packed pairs)
#define QBLOCKS (NROWS / (ATHREADS * QPT))  // 64

typedef unsigned long long u64;

// Scratch (__device__ globals; no allocation allowed).
__device__ float4 g_Qs[NROWS];        // Q pre-scaled by 0.5*log2(e)
__device__ float4 g_Kd[2 * NROWS];    // duplicated: [k0,k0,k1,k1],[k2,k2,k3,k3]
__device__ float4 g_Vd[2 * NROWS];
// Partials: 3 planes of {KSPLIT x NPAIRS} float4.
// plane0={denA,denB,a0A,a0B} plane1={a1A,a1B,a2A,a2B} plane2={a3A,a3B,-,-}
__device__ float4 g_part[3 * KSPLIT * NPAIRS];

// ---- f32x2 helpers ----
__device__ __forceinline__ u64 pack2(float lo, float hi) {
    u64 r; asm("mov.b64 %0, {%1, %2};" : "=l"(r) : "f"(lo), "f"(hi)); return r;
}
__device__ __forceinline__ void unpack2(u64 v, float& lo, float& hi) {
    asm("mov.b64 {%0, %1}, %2;" : "=f"(lo), "=f"(hi) : "l"(v));
}
__device__ __forceinline__ u64 mul2(u64 a, u64 b) {
    u64 r; asm("mul.rn.f32x2 %0, %1, %2;" : "=l"(r) : "l"(a), "l"(b)); return r;
}
__device__ __forceinline__ void fma2(u64& d, u64 a, u64 b) {
    asm("fma.rn.f32x2 %0, %1, %2, %0;" : "+l"(d) : "l"(a), "l"(b));
}
__device__ __forceinline__ void add2(u64& d, u64 a) {
    asm("add.rn.f32x2 %0, %1, %0;" : "+l"(d) : "l"(a));
}
__device__ __forceinline__ float ex2f(float x) {
    float r; asm("ex2.approx.f32 %0, %1;" : "=f"(r) : "f"(x)); return r;
}

// Collapsed circuit: partial products of cos(x_q + w_q).
__device__ __forceinline__ float4 circuit4(float4 x, const float* w) {
    float u0 = __cosf(x.x + w[0]);
    float u1 = __cosf(x.y + w[1]);
    float u2 = __cosf(x.z + w[2]);
    float u3 = __cosf(x.w + w[3]);
    float4 r;
    r.y = u0 * u1;
    r.z = r.y * u2;
    r.w = r.z * u3;
    r.x = u1 * u2 * u3;
    return r;
}

__global__ void __launch_bounds__(256) qkv_kernel(
    const float* __restrict__ x,
    const float* __restrict__ wQ,
    const float* __restrict__ wK,
    const float* __restrict__ wV)
{
    int n = blockIdx.x * blockDim.x + threadIdx.x;
    float4 xv = reinterpret_cast<const float4*>(x)[n];
    const float ALPHA = 0.72134752044448170367f;  // 0.5 * log2(e)
    float4 q = circuit4(xv, wQ);
    q.x *= ALPHA; q.y *= ALPHA; q.z *= ALPHA; q.w *= ALPHA;
    g_Qs[n] = q;
    float4 k = circuit4(xv, wK);
    g_Kd[2*n]   = make_float4(k.x, k.x, k.y, k.y);
    g_Kd[2*n+1] = make_float4(k.z, k.z, k.w, k.w);
    float4 v = circuit4(xv, wV);
    g_Vd[2*n]   = make_float4(v.x, v.x, v.y, v.y);
    g_Vd[2*n+1] = make_float4(v.z, v.z, v.w, v.w);
}

__global__ void __launch_bounds__(ATHREADS) attn_kernel()
{
    __shared__ float4 sK[2 * KEYS];
    __shared__ float4 sV[2 * KEYS];

    int qb = blockIdx.x;              // 0..63: 1024-query tile
    int split = blockIdx.y;           // 0..7
    int b = qb >> 1;                  // batch
    int kbase = b * NS + split * KEYS;

    for (int i = threadIdx.x; i < KEYS; i += ATHREADS) {
        sK[2*i]   = g_Kd[2*(kbase+i)];
        sK[2*i+1] = g_Kd[2*(kbase+i)+1];
        sV[2*i]   = g_Vd[2*(kbase+i)];
        sV[2*i+1] = g_Vd[2*(kbase+i)+1];
    }

    int base = qb * (ATHREADS * QPT) + threadIdx.x * QPT;
    u64 Q[4][4];
    #pragma unroll
    for (int p = 0; p < 4; p++) {
        float4 qa = g_Qs[base + 2*p];
        float4 qb4 = g_Qs[base + 2*p + 1];
        Q[p][0] = pack2(qa.x, qb4.x);
        Q[p][1] = pack2(qa.y, qb4.y);
        Q[p][2] = pack2(qa.z, qb4.z);
        Q[p][3] = pack2(qa.w, qb4.w);
    }

    u64 den[4] = {0,0,0,0};
    u64 acc[4][4] = {};

    __syncthreads();

    const ulonglong2* sK2 = reinterpret_cast<const ulonglong2*>(sK);
    const ulonglong2* sV2 = reinterpret_cast<const ulonglong2*>(sV);

    #pragma unroll 4
    for (int j = 0; j < KEYS; j++) {
        ulonglong2 k01 = sK2[2*j];      // [k0,k0] [k1,k1]
        ulonglong2 k23 = sK2[2*j+1];    // [k2,k2] [k3,k3]
        ulonglong2 v01 = sV2[2*j];
        ulonglong2 v23 = sV2[2*j+1];
        #pragma unroll
        for (int p = 0; p < 4; p++) {
            u64 s = mul2(Q[p][0], k01.x);
            fma2(s, Q[p][1], k01.y);
            fma2(s, Q[p][2], k23.x);
            fma2(s, Q[p][3], k23.y);
            float sA, sB;
            unpack2(s, sA, sB);
            u64 w = pack2(ex2f(sA), ex2f(sB));
            add2(den[p], w);
            fma2(acc[p][0], w, v01.x);
            fma2(acc[p][1], w, v01.y);
            fma2(acc[p][2], w, v23.x);
            fma2(acc[p][3], w, v23.y);
        }
    }

    #pragma unroll
    for (int p = 0; p < 4; p++) {
        int pg = (base >> 1) + p;
        float dA, dB, a0A, a0B, a1A, a1B, a2A, a2B, a3A, a3B;
        unpack2(den[p], dA, dB);
        unpack2(acc[p][0], a0A, a0B);
        unpack2(acc[p][1], a1A, a1B);
        unpack2(acc[p][2], a2A, a2B);
        unpack2(acc[p][3], a3A, a3B);
        g_part[(0*KSPLIT + split)*NPAIRS + pg] = make_float4(dA, dB, a0A, a0B);
        g_part[(1*KSPLIT + split)*NPAIRS + pg] = make_float4(a1A, a1B, a2A, a2B);
        g_part[(2*KSPLIT + split)*NPAIRS + pg] = make_float4(a3A, a3B, 0.f, 0.f);
    }
}

__global__ void __launch_bounds__(256) combine_kernel(
    const float* __restrict__ wC, float* __restrict__ out)
{
    int p = blockIdx.x * blockDim.x + threadIdx.x;  // query pair
    float4 s0 = make_float4(0,0,0,0), s1 = s0, s2 = s0;
    #pragma unroll
    for (int s = 0; s < KSPLIT; s++) {
        float4 t0 = g_part[(0*KSPLIT + s)*NPAIRS + p];
        float4 t1 = g_part[(1*KSPLIT + s)*NPAIRS + p];
        float4 t2 = g_part[(2*KSPLIT + s)*NPAIRS + p];
        s0.x += t0.x; s0.y += t0.y; s0.z += t0.z; s0.w += t0.w;
        s1.x += t1.x; s1.y += t1.y; s1.z += t1.z; s1.w += t1.w;
        s2.x += t2.x; s2.y += t2.y;
    }
    float invA = 1.0f / s0.x;
    float invB = 1.0f / s0.y;
    float4 ctxA = make_float4(s0.z*invA, s1.x*invA, s1.z*invA, s2.x*invA);
    float4 ctxB = make_float4(s0.w*invB, s1.y*invB, s1.w*invB, s2.y*invB);
    float4* o4 = reinterpret_cast<float4*>(out);
    o4[2*p]   = circuit4(ctxA, wC);
    o4[2*p+1] = circuit4(ctxB, wC);
}

extern "C" void kernel_launch(void* const* d_in, const int* in_sizes, int n_in,
                              void* d_out, int out_size)
{
    const float* x  = (const float*)d_in[0];
    const float* wQ = (const float*)d_in[1];
    const float* wK = (const float*)d_in[2];
    const float* wV = (const float*)d_in[3];
    const float* wC = (const float*)d_in[4];
    float* out = (float*)d_out;

    qkv_kernel<<<NROWS / 256, 256>>>(x, wQ, wK, wV);
    attn_kernel<<<dim3(QBLOCKS, KSPLIT), ATHREADS>>>();
    combine_kernel<<<NPAIRS / 256, 256>>>(wC, out);
}

// round 3
// speedup vs baseline: 1.0323x; 1.0052x over previous
#include <cuda_runtime.h>

// Shape fixed by setup_inputs: B=32, S=2048, E=NQ=4.
#define NB 32
#define NS 2048
#define NROWS (NB * NS)          // 65536 queries
#define NPAIRS (NROWS / 2)       // 32768 query pairs
#define KSPLIT 8
#define KEYS (NS / KSPLIT)       // 256 keys per split block
#define ATHREADS 256             // attn threads/block (8 warps: occupancy fix)
#define QPT 4                    // queries per thread (2 packed pairs)
#define QBLOCKS (NROWS / (ATHREADS * QPT))  // 64

typedef unsigned long long u64;

// Scratch (__device__ globals; no allocation allowed).
__device__ float4 g_Qs[NROWS];        // Q pre-scaled by 0.5*log2(e)
__device__ float4 g_Kd[2 * NROWS];    // duplicated: [k0,k0,k1,k1],[k2,k2,k3,k3]
__device__ float4 g_Vd[2 * NROWS];
// Partials: 3 planes of {KSPLIT x NPAIRS} float4.
__device__ float4 g_part[3 * KSPLIT * NPAIRS];

// ---- f32x2 helpers ----
__device__ __forceinline__ u64 pack2(float lo, float hi) {
    u64 r; asm("mov.b64 %0, {%1, %2};" : "=l"(r) : "f"(lo), "f"(hi)); return r;
}
__device__ __forceinline__ void unpack2(u64 v, float& lo, float& hi) {
    asm("mov.b64 {%0, %1}, %2;" : "=f"(lo), "=f"(hi) : "l"(v));
}
__device__ __forceinline__ u64 mul2(u64 a, u64 b) {
    u64 r; asm("mul.rn.f32x2 %0, %1, %2;" : "=l"(r) : "l"(a), "l"(b)); return r;
}
__device__ __forceinline__ void fma2(u64& d, u64 a, u64 b) {
    asm("fma.rn.f32x2 %0, %1, %2, %0;" : "+l"(d) : "l"(a), "l"(b));
}
__device__ __forceinline__ void add2(u64& d, u64 a) {
    asm("add.rn.f32x2 %0, %1, %0;" : "+l"(d) : "l"(a));
}
__device__ __forceinline__ float ex2f(float x) {
    float r; asm("ex2.approx.f32 %0, %1;" : "=f"(r) : "f"(x)); return r;
}

// Collapsed circuit: partial products of cos(x_q + w_q).
__device__ __forceinline__ float4 circuit4(float4 x, const float* w) {
    float u0 = __cosf(x.x + w[0]);
    float u1 = __cosf(x.y + w[1]);
    float u2 = __cosf(x.z + w[2]);
    float u3 = __cosf(x.w + w[3]);
    float4 r;
    r.y = u0 * u1;
    r.z = r.y * u2;
    r.w = r.z * u3;
    r.x = u1 * u2 * u3;
    return r;
}

__global__ void __launch_bounds__(256) qkv_kernel(
    const float* __restrict__ x,
    const float* __restrict__ wQ,
    const float* __restrict__ wK,
    const float* __restrict__ wV)
{
    int n = blockIdx.x * blockDim.x + threadIdx.x;
    float4 xv = reinterpret_cast<const float4*>(x)[n];
    const float ALPHA = 0.72134752044448170367f;  // 0.5 * log2(e)
    float4 q = circuit4(xv, wQ);
    q.x *= ALPHA; q.y *= ALPHA; q.z *= ALPHA; q.w *= ALPHA;
    g_Qs[n] = q;
    float4 k = circuit4(xv, wK);
    g_Kd[2*n]   = make_float4(k.x, k.x, k.y, k.y);
    g_Kd[2*n+1] = make_float4(k.z, k.z, k.w, k.w);
    float4 v = circuit4(xv, wV);
    g_Vd[2*n]   = make_float4(v.x, v.x, v.y, v.y);
    g_Vd[2*n+1] = make_float4(v.z, v.z, v.w, v.w);
}

__global__ void __launch_bounds__(ATHREADS) attn_kernel()
{
    __shared__ float4 sK[2 * KEYS];   // 8 KB
    __shared__ float4 sV[2 * KEYS];   // 8 KB

    int qb = blockIdx.x;              // 0..63: 1024-query tile
    int split = blockIdx.y;           // 0..7
    int b = qb >> 1;                  // batch
    int kbase = b * NS + split * KEYS;

    for (int i = threadIdx.x; i < KEYS; i += ATHREADS) {
        sK[2*i]   = g_Kd[2*(kbase+i)];
        sK[2*i+1] = g_Kd[2*(kbase+i)+1];
        sV[2*i]   = g_Vd[2*(kbase+i)];
        sV[2*i+1] = g_Vd[2*(kbase+i)+1];
    }

    int base = qb * (ATHREADS * QPT) + threadIdx.x * QPT;
    u64 Q[2][4];
    #pragma unroll
    for (int p = 0; p < 2; p++) {
        float4 qa = g_Qs[base + 2*p];
        float4 qc = g_Qs[base + 2*p + 1];
        Q[p][0] = pack2(qa.x, qc.x);
        Q[p][1] = pack2(qa.y, qc.y);
        Q[p][2] = pack2(qa.z, qc.z);
        Q[p][3] = pack2(qa.w, qc.w);
    }

    u64 den[2] = {0,0};
    u64 acc[2][4] = {};

    __syncthreads();

    const ulonglong2* sK2 = reinterpret_cast<const ulonglong2*>(sK);
    const ulonglong2* sV2 = reinterpret_cast<const ulonglong2*>(sV);

    #pragma unroll 4
    for (int j = 0; j < KEYS; j++) {
        ulonglong2 k01 = sK2[2*j];      // [k0,k0] [k1,k1]
        ulonglong2 k23 = sK2[2*j+1];    // [k2,k2] [k3,k3]
        ulonglong2 v01 = sV2[2*j];
        ulonglong2 v23 = sV2[2*j+1];
        #pragma unroll
        for (int p = 0; p < 2; p++) {
            u64 s = mul2(Q[p][0], k01.x);
            fma2(s, Q[p][1], k01.y);
            fma2(s, Q[p][2], k23.x);
            fma2(s, Q[p][3], k23.y);
            float sA, sB;
            unpack2(s, sA, sB);
            u64 w = pack2(ex2f(sA), ex2f(sB));
            add2(den[p], w);
            fma2(acc[p][0], w, v01.x);
            fma2(acc[p][1], w, v01.y);
            fma2(acc[p][2], w, v23.x);
            fma2(acc[p][3], w, v23.y);
        }
    }

    #pragma unroll
    for (int p = 0; p < 2; p++) {
        int pg = (base >> 1) + p;
        float dA, dB, a0A, a0B, a1A, a1B, a2A, a2B, a3A, a3B;
        unpack2(den[p], dA, dB);
        unpack2(acc[p][0], a0A, a0B);
        unpack2(acc[p][1], a1A, a1B);
        unpack2(acc[p][2], a2A, a2B);
        unpack2(acc[p][3], a3A, a3B);
        g_part[(0*KSPLIT + split)*NPAIRS + pg] = make_float4(dA, dB, a0A, a0B);
        g_part[(1*KSPLIT + split)*NPAIRS + pg] = make_float4(a1A, a1B, a2A, a2B);
        g_part[(2*KSPLIT + split)*NPAIRS + pg] = make_float4(a3A, a3B, 0.f, 0.f);
    }
}

__global__ void __launch_bounds__(256) combine_kernel(
    const float* __restrict__ wC, float* __restrict__ out)
{
    int p = blockIdx.x * blockDim.x + threadIdx.x;  // query pair
    float4 s0 = make_float4(0,0,0,0), s1 = s0, s2 = s0;
    #pragma unroll
    for (int s = 0; s < KSPLIT; s++) {
        float4 t0 = g_part[(0*KSPLIT + s)*NPAIRS + p];
        float4 t1 = g_part[(1*KSPLIT + s)*NPAIRS + p];
        float4 t2 = g_part[(2*KSPLIT + s)*NPAIRS + p];
        s0.x += t0.x; s0.y += t0.y; s0.z += t0.z; s0.w += t0.w;
        s1.x += t1.x; s1.y += t1.y; s1.z += t1.z; s1.w += t1.w;
        s2.x += t2.x; s2.y += t2.y;
    }
    float invA = 1.0f / s0.x;
    float invB = 1.0f / s0.y;
    float4 ctxA = make_float4(s0.z*invA, s1.x*invA, s1.z*invA, s2.x*invA);
    float4 ctxB = make_float4(s0.w*invB, s1.y*invB, s1.w*invB, s2.y*invB);
    float4* o4 = reinterpret_cast<float4*>(out);
    o4[2*p]   = circuit4(ctxA, wC);
    o4[2*p+1] = circuit4(ctxB, wC);
}

extern "C" void kernel_launch(void* const* d_in, const int* in_sizes, int n_in,
                              void* d_out, int out_size)
{
    const float* x  = (const float*)d_in[0];
    const float* wQ = (const float*)d_in[1];
    const float* wK = (const float*)d_in[2];
    const float* wV = (const float*)d_in[3];
    const float* wC = (const float*)d_in[4];
    float* out = (float*)d_out;

    qkv_kernel<<<NROWS / 256, 256>>>(x, wQ, wK, wV);
    attn_kernel<<<dim3(QBLOCKS, KSPLIT), ATHREADS>>>();
    combine_kernel<<<NPAIRS / 256, 256>>>(wC, out);
}

// round 5
// speedup vs baseline: 1.5317x; 1.4837x over previous
#include <cuda_runtime.h>
#include <cuda_fp16.h>

// Shape fixed by setup_inputs: B=32, S=2048, E=NQ=4.
#define NB 32
#define NS 2048
#define NROWS (NB * NS)          // 65536 queries
#define NPAIRS (NROWS / 2)       // 32768 query pairs
#define KSPLIT 8
#define KEYS (NS / KSPLIT)       // 256 keys per split block
#define CHUNK 16                 // fp16 accumulation chunk (precision guard)
#define ATHREADS 256
#define QPT 4                    // queries per thread = 2 half2 pairs
#define QBLOCKS (NROWS / (ATHREADS * QPT))  // 64

// Scratch (__device__ globals; no allocation allowed).
__device__ uint4 g_Qh[NPAIRS];        // per pair: 4x half2 (qA_e, qB_e), pre-scaled by 0.5*log2(e)
__device__ uint4 g_Kh[NROWS];         // per row: 4x half2 (k_e, k_e)
__device__ uint4 g_Vh[NROWS];         // per row: 4x half2 (v_e, v_e)
// Partials: 3 planes of {KSPLIT x NPAIRS} float4.
// plane0={denA,denB,a0A,a0B} plane1={a1A,a1B,a2A,a2B} plane2={a3A,a3B,-,-}
__device__ float4 g_part[3 * KSPLIT * NPAIRS];

__device__ __forceinline__ __half2 qexp2_h2(__half2 x) {
    unsigned xi = *reinterpret_cast<unsigned*>(&x);
    unsigned ri;
    asm("ex2.approx.f16x2 %0, %1;" : "=r"(ri) : "r"(xi));
    return *reinterpret_cast<__half2*>(&ri);
}

// Collapsed circuit: partial products of cos(x_q + w_q).
__device__ __forceinline__ float4 circuit4(float4 x, const float* w) {
    float u0 = __cosf(x.x + w[0]);
    float u1 = __cosf(x.y + w[1]);
    float u2 = __cosf(x.z + w[2]);
    float u3 = __cosf(x.w + w[3]);
    float4 r;
    r.y = u0 * u1;
    r.z = r.y * u2;
    r.w = r.z * u3;
    r.x = u1 * u2 * u3;
    return r;
}

__device__ __forceinline__ uint4 dup4(float4 a) {
    __half2 h0 = __floats2half2_rn(a.x, a.x);
    __half2 h1 = __floats2half2_rn(a.y, a.y);
    __half2 h2 = __floats2half2_rn(a.z, a.z);
    __half2 h3 = __floats2half2_rn(a.w, a.w);
    uint4 r;
    r.x = *reinterpret_cast<unsigned*>(&h0);
    r.y = *reinterpret_cast<unsigned*>(&h1);
    r.z = *reinterpret_cast<unsigned*>(&h2);
    r.w = *reinterpret_cast<unsigned*>(&h3);
    return r;
}

__global__ void __launch_bounds__(128) qkv_kernel(
    const float* __restrict__ x,
    const float* __restrict__ wQ,
    const float* __restrict__ wK,
    const float* __restrict__ wV)
{
    int p = blockIdx.x * blockDim.x + threadIdx.x;  // query pair
    int r0 = 2 * p, r1 = 2 * p + 1;
    float4 xa = reinterpret_cast<const float4*>(x)[r0];
    float4 xb = reinterpret_cast<const float4*>(x)[r1];

    const float ALPHA = 0.72134752044448170367f;  // 0.5 * log2(e)
    float4 qa = circuit4(xa, wQ);
    float4 qb = circuit4(xb, wQ);
    __half2 q0 = __floats2half2_rn(qa.x * ALPHA, qb.x * ALPHA);
    __half2 q1 = __floats2half2_rn(qa.y * ALPHA, qb.y * ALPHA);
    __half2 q2 = __floats2half2_rn(qa.z * ALPHA, qb.z * ALPHA);
    __half2 q3 = __floats2half2_rn(qa.w * ALPHA, qb.w * ALPHA);
    uint4 qh;
    qh.x = *reinterpret_cast<unsigned*>(&q0);
    qh.y = *reinterpret_cast<unsigned*>(&q1);
    qh.z = *reinterpret_cast<unsigned*>(&q2);
    qh.w = *reinterpret_cast<unsigned*>(&q3);
    g_Qh[p] = qh;

    g_Kh[r0] = dup4(circuit4(xa, wK));
    g_Kh[r1] = dup4(circuit4(xb, wK));
    g_Vh[r0] = dup4(circuit4(xa, wV));
    g_Vh[r1] = dup4(circuit4(xb, wV));
}

__global__ void __launch_bounds__(ATHREADS) attn_kernel()
{
    __shared__ uint4 sK[KEYS];   // 4 KB
    __shared__ uint4 sV[KEYS];   // 4 KB

    int qb = blockIdx.x;              // 0..63: 1024-query tile
    int split = blockIdx.y;           // 0..7
    int b = qb >> 1;                  // batch (2 blocks per batch)
    int kbase = b * NS + split * KEYS;

    for (int i = threadIdx.x; i < KEYS; i += ATHREADS) {
        sK[i] = g_Kh[kbase + i];
        sV[i] = g_Vh[kbase + i];
    }

    int pb = qb * (ATHREADS * 2) + threadIdx.x * 2;   // first of 2 pairs
    __half2 Q[2][4];
    #pragma unroll
    for (int p = 0; p < 2; p++) {
        uint4 qh = g_Qh[pb + p];
        Q[p][0] = *reinterpret_cast<__half2*>(&qh.x);
        Q[p][1] = *reinterpret_cast<__half2*>(&qh.y);
        Q[p][2] = *reinterpret_cast<__half2*>(&qh.z);
        Q[p][3] = *reinterpret_cast<__half2*>(&qh.w);
    }

    float2 denf[2] = {{0.f,0.f},{0.f,0.f}};
    float2 accf[2][4] = {};

    __syncthreads();

    #pragma unroll 1
    for (int c0 = 0; c0 < KEYS; c0 += CHUNK) {
        __half2 hz = __floats2half2_rn(0.f, 0.f);
        __half2 hden[2] = {hz, hz};
        __half2 hacc[2][4] = {{hz,hz,hz,hz},{hz,hz,hz,hz}};

        #pragma unroll
        for (int j = 0; j < CHUNK; j++) {
            uint4 kk = sK[c0 + j];
            uint4 vv = sV[c0 + j];
            __half2 k0 = *reinterpret_cast<__half2*>(&kk.x);
            __half2 k1 = *reinterpret_cast<__half2*>(&kk.y);
            __half2 k2 = *reinterpret_cast<__half2*>(&kk.z);
            __half2 k3 = *reinterpret_cast<__half2*>(&kk.w);
            __half2 v0 = *reinterpret_cast<__half2*>(&vv.x);
            __half2 v1 = *reinterpret_cast<__half2*>(&vv.y);
            __half2 v2 = *reinterpret_cast<__half2*>(&vv.z);
            __half2 v3 = *reinterpret_cast<__half2*>(&vv.w);
            #pragma unroll
            for (int p = 0; p < 2; p++) {
                __half2 s = __hmul2(Q[p][0], k0);
                s = __hfma2(Q[p][1], k1, s);
                s = __hfma2(Q[p][2], k2, s);
                s = __hfma2(Q[p][3], k3, s);
                __half2 w = qexp2_h2(s);
                hden[p] = __hadd2(hden[p], w);
                hacc[p][0] = __hfma2(w, v0, hacc[p][0]);
                hacc[p][1] = __hfma2(w, v1, hacc[p][1]);
                hacc[p][2] = __hfma2(w, v2, hacc[p][2]);
                hacc[p][3] = __hfma2(w, v3, hacc[p][3]);
            }
        }
        // Promote chunk sums into f32 accumulators.
        #pragma unroll
        for (int p = 0; p < 2; p++) {
            float2 d = __half22float2(hden[p]);
            denf[p].x += d.x; denf[p].y += d.y;
            #pragma unroll
            for (int e = 0; e < 4; e++) {
                float2 a = __half22float2(hacc[p][e]);
                accf[p][e].x += a.x; accf[p][e].y += a.y;
            }
        }
    }

    #pragma unroll
    for (int p = 0; p < 2; p++) {
        int pg = pb + p;
        g_part[(0*KSPLIT + split)*NPAIRS + pg] =
            make_float4(denf[p].x, denf[p].y, accf[p][0].x, accf[p][0].y);
        g_part[(1*KSPLIT + split)*NPAIRS + pg] =
            make_float4(accf[p][1].x, accf[p][1].y, accf[p][2].x, accf[p][2].y);
        g_part[(2*KSPLIT + split)*NPAIRS + pg] =
            make_float4(accf[p][3].x, accf[p][3].y, 0.f, 0.f);
    }
}

__global__ void __launch_bounds__(256) combine_kernel(
    const float* __restrict__ wC, float* __restrict__ out)
{
    int p = blockIdx.x * blockDim.x + threadIdx.x;  // query pair
    float4 s0 = make_float4(0,0,0,0), s1 = s0, s2 = s0;
    #pragma unroll
    for (int s = 0; s < KSPLIT; s++) {
        float4 t0 = g_part[(0*KSPLIT + s)*NPAIRS + p];
        float4 t1 = g_part[(1*KSPLIT + s)*NPAIRS + p];
        float4 t2 = g_part[(2*KSPLIT + s)*NPAIRS + p];
        s0.x += t0.x; s0.y += t0.y; s0.z += t0.z; s0.w += t0.w;
        s1.x += t1.x; s1.y += t1.y; s1.z += t1.z; s1.w += t1.w;
        s2.x += t2.x; s2.y += t2.y;
    }
    float invA = 1.0f / s0.x;
    float invB = 1.0f / s0.y;
    float4 ctxA = make_float4(s0.z*invA, s1.x*invA, s1.z*invA, s2.x*invA);
    float4 ctxB = make_float4(s0.w*invB, s1.y*invB, s1.w*invB, s2.y*invB);
    float4* o4 = reinterpret_cast<float4*>(out);
    o4[2*p]   = circuit4(ctxA, wC);
    o4[2*p+1] = circuit4(ctxB, wC);
}

extern "C" void kernel_launch(void* const* d_in, const int* in_sizes, int n_in,
                              void* d_out, int out_size)
{
    const float* x  = (const float*)d_in[0];
    const float* wQ = (const float*)d_in[1];
    const float* wK = (const float*)d_in[2];
    const float* wV = (const float*)d_in[3];
    const float* wC = (const float*)d_in[4];
    float* out = (float*)d_out;

    qkv_kernel<<<NPAIRS / 128, 128>>>(x, wQ, wK, wV);
    attn_kernel<<<dim3(QBLOCKS, KSPLIT), ATHREADS>>>();
    combine_kernel<<<NPAIRS / 256, 256>>>(wC, out);
}

// round 6
// speedup vs baseline: 2.8366x; 1.8520x over previous
#include <cuda_runtime.h>
#include <cuda_fp16.h>

// Shape fixed by setup_inputs: B=32, S=2048, E=NQ=4.
#define NB 32
#define NS 2048
#define NROWS (NB * NS)   // 65536

// MMA fragment-layout scratch (no allocation allowed -> __device__ globals).
// Q A-frags:  [b][qg=128][lane=32][j=2]  u32 (half2)       -> 1 MB
// K B-frags:  [b][g4=64][lane=32][j=4]   u32 (half2)       -> 1 MB
// V' B-frags: same shape but written per-half (two keys share a word) -> 1 MB
__device__ unsigned g_qf[NB * 128 * 32 * 2];
__device__ unsigned g_kf[NB * 64 * 32 * 4];
__device__ __align__(16) __half g_vf[NB * 64 * 32 * 4 * 2];

// Collapsed circuit: partial products of cos(x_q + w_q).
__device__ __forceinline__ float4 circuit4(float4 x, const float* w) {
    float u0 = __cosf(x.x + w[0]);
    float u1 = __cosf(x.y + w[1]);
    float u2 = __cosf(x.z + w[2]);
    float u3 = __cosf(x.w + w[3]);
    float4 r;
    r.y = u0 * u1;
    r.z = r.y * u2;
    r.w = r.z * u3;
    r.x = u1 * u2 * u3;
    return r;
}

__device__ __forceinline__ unsigned packh2(float lo, float hi) {
    __half2 h = __floats2half2_rn(lo, hi);
    return *reinterpret_cast<unsigned*>(&h);
}

// One thread per row: emit Q/K/V already in m16n8k8 fragment layout.
__global__ void __launch_bounds__(256) qkv_kernel(
    const float* __restrict__ x,
    const float* __restrict__ wQ,
    const float* __restrict__ wK,
    const float* __restrict__ wV)
{
    int n = blockIdx.x * 256 + threadIdx.x;
    int b = n >> 11, kl = n & 2047;
    float4 xv = reinterpret_cast<const float4*>(x)[n];
    const float ALPHA = 0.72134752044448170367f;  // 0.5 * log2(e), folded into Q

    // ---- Q: A-fragment. row r=kl%16 within 16-query group qg.
    {
        float4 q = circuit4(xv, wQ);
        int qg = kl >> 4, r = kl & 15;
        int j = r >> 3, rb = r & 7;              // a0 (rows 0-7) or a1 (rows 8-15)
        unsigned base = (((b * 128 + qg) * 32) + rb * 4) * 2 + j;
        g_qf[base]     = packh2(q.x * ALPHA, q.y * ALPHA);  // lane%4==0: cols 0,1
        g_qf[base + 2] = packh2(q.z * ALPHA, q.w * ALPHA);  // lane%4==1: cols 2,3
        g_qf[base + 4] = 0;                                  // k-dim pad (cols 4-7)
        g_qf[base + 6] = 0;
    }
    // ---- K: B-fragment of QK^T. key slot s=kl%8 -> column s -> lanes s*4+{0..3}.
    {
        float4 k = circuit4(xv, wK);
        int g = kl >> 3, s = kl & 7;
        int g4 = g >> 2, j = g & 3;
        unsigned base = ((((b * 64 + g4) * 32) + s * 4) * 4) + j;
        g_kf[base]      = packh2(k.x, k.y);   // rows 0,1
        g_kf[base + 4]  = packh2(k.z, k.w);   // rows 2,3
        g_kf[base + 8]  = 0;                  // rows 4-7 pad
        g_kf[base + 12] = 0;
    }
    // ---- V': B-fragment of P@V'. rows = keys (8 real), cols = {v0..v3, 1, 0,0,0}.
    // word(lane=c*4+s/2, j) halves: lo = key (s even), hi = key (s odd).
    {
        float4 v = circuit4(xv, wV);
        int g = kl >> 3, s = kl & 7;
        int g4 = g >> 2, j = g & 3;
        int h = s & 1, sp = s >> 1;
        unsigned rowbase = (b * 64 + g4) * 32;
        float vals[8] = {v.x, v.y, v.z, v.w, 1.0f, 0.f, 0.f, 0.f};
        #pragma unroll
        for (int c = 0; c < 8; c++) {
            g_vf[(((rowbase + c * 4 + sp) * 4) + j) * 2 + h] = __float2half(vals[c]);
        }
    }
}

// One 8-key MMA step: S = Q*K^T (f32), P = exp(S) (f16x2), acc += P*V'.
__device__ __forceinline__ void mma_step(uint2 aq, unsigned kb, unsigned vb,
                                         float& d0, float& d1, float& d2, float& d3)
{
    float s0, s1, s2, s3;
    asm("mma.sync.aligned.m16n8k8.row.col.f32.f16.f16.f32 "
        "{%0,%1,%2,%3}, {%4,%5}, {%6}, {%7,%8,%9,%10};"
        : "=f"(s0), "=f"(s1), "=f"(s2), "=f"(s3)
        : "r"(aq.x), "r"(aq.y), "r"(kb),
          "f"(0.f), "f"(0.f), "f"(0.f), "f"(0.f));
    unsigned p01, p23;
    asm("cvt.rn.f16x2.f32 %0, %1, %2;" : "=r"(p01) : "f"(s1), "f"(s0));  // lo=s0 hi=s1
    asm("cvt.rn.f16x2.f32 %0, %1, %2;" : "=r"(p23) : "f"(s3), "f"(s2));
    asm("ex2.approx.f16x2 %0, %1;" : "=r"(p01) : "r"(p01));
    asm("ex2.approx.f16x2 %0, %1;" : "=r"(p23) : "r"(p23));
    asm("mma.sync.aligned.m16n8k8.row.col.f32.f16.f16.f32 "
        "{%0,%1,%2,%3}, {%4,%5}, {%6}, {%0,%1,%2,%3};"
        : "+f"(d0), "+f"(d1), "+f"(d2), "+f"(d3)
        : "r"(p01), "r"(p23), "r"(vb));
}

#define CHUNK_G4 16   // 16 uint4-groups = 64 key-groups = 512 keys per stage

__global__ void __launch_bounds__(256) attn_kernel(
    const float* __restrict__ wC, float* __restrict__ out)
{
    __shared__ uint4 sK[CHUNK_G4 * 32];       // 8 KB
    __shared__ uint4 sV[CHUNK_G4 * 32];       // 8 KB
    __shared__ float epi[8][16][6];           // 3 KB

    int b = blockIdx.y;
    int w = threadIdx.x >> 5, lane = threadIdx.x & 31;
    int qg = blockIdx.x * 8 + w;              // 16-query group

    uint2 aq = reinterpret_cast<const uint2*>(g_qf)[(b * 128 + qg) * 32 + lane];

    float d0 = 0.f, d1 = 0.f, d2 = 0.f, d3 = 0.f;

    for (int c = 0; c < 4; c++) {
        __syncthreads();
        const uint4* gk = reinterpret_cast<const uint4*>(g_kf) + (b * 64 + c * CHUNK_G4) * 32;
        const uint4* gv = reinterpret_cast<const uint4*>(g_vf) + (b * 64 + c * CHUNK_G4) * 32;
        sK[threadIdx.x]       = gk[threadIdx.x];
        sK[threadIdx.x + 256] = gk[threadIdx.x + 256];
        sV[threadIdx.x]       = gv[threadIdx.x];
        sV[threadIdx.x + 256] = gv[threadIdx.x + 256];
        __syncthreads();
        #pragma unroll 4
        for (int g4 = 0; g4 < CHUNK_G4; g4++) {
            uint4 kk = sK[g4 * 32 + lane];
            uint4 vv = sV[g4 * 32 + lane];
            mma_step(aq, kk.x, vv.x, d0, d1, d2, d3);
            mma_step(aq, kk.y, vv.y, d0, d1, d2, d3);
            mma_step(aq, kk.z, vv.z, d0, d1, d2, d3);
            mma_step(aq, kk.w, vv.w, d0, d1, d2, d3);
        }
    }

    // Epilogue: C cols per lane%4: 0->(v0,v1) 1->(v2,v3) 2->(den,_) 3->(_,_)
    int r = lane >> 2, q4 = lane & 3;
    if (q4 == 0) {
        epi[w][r][0] = d0; epi[w][r][1] = d1;
        epi[w][r + 8][0] = d2; epi[w][r + 8][1] = d3;
    } else if (q4 == 1) {
        epi[w][r][2] = d0; epi[w][r][3] = d1;
        epi[w][r + 8][2] = d2; epi[w][r + 8][3] = d3;
    } else if (q4 == 2) {
        epi[w][r][4] = d0;
        epi[w][r + 8][4] = d2;
    }
    __syncwarp();
    if (lane < 16) {
        float inv = 1.0f / epi[w][lane][4];
        float4 ctx = make_float4(epi[w][lane][0] * inv, epi[w][lane][1] * inv,
                                 epi[w][lane][2] * inv, epi[w][lane][3] * inv);
        int n = b * NS + qg * 16 + lane;
        reinterpret_cast<float4*>(out)[n] = circuit4(ctx, wC);
    }
}

extern "C" void kernel_launch(void* const* d_in, const int* in_sizes, int n_in,
                              void* d_out, int out_size)
{
    const float* x  = (const float*)d_in[0];
    const float* wQ = (const float*)d_in[1];
    const float* wK = (const float*)d_in[2];
    const float* wV = (const float*)d_in[3];
    const float* wC = (const float*)d_in[4];
    float* out = (float*)d_out;

    qkv_kernel<<<NROWS / 256, 256>>>(x, wQ, wK, wV);
    attn_kernel<<<dim3(16, NB), 256>>>(wC, out);
}

// round 8
// speedup vs baseline: 3.1019x; 1.0935x over previous
#include <cuda_runtime.h>
#include <cuda_fp16.h>

// Shape fixed by setup_inputs: B=32, S=2048, E=NQ=4.
#define NB 32
#define NS 2048
#define NROWS (NB * NS)   // 65536
#define KSPLIT 2
#define CHUNK_G4 16       // 16 uint4 rows = 64 key-groups = 512 keys per stage

// MMA fragment-layout scratch (no allocation -> __device__ globals).
__device__ unsigned g_qf[NB * 128 * 32 * 2];   // Q A-frags
__device__ unsigned g_kf[NB * 64 * 32 * 4];    // K B-frags
__device__ unsigned g_vf[NB * 64 * 32 * 4];    // V' B-frags (half2 words)
// Split-K partials.
__device__ float4 g_pv[KSPLIT * NROWS];
__device__ float  g_pd[KSPLIT * NROWS];

// Collapsed circuit: partial products of cos(x_q + w_q).
__device__ __forceinline__ float4 circuit4(float4 x, const float* w) {
    float u0 = __cosf(x.x + w[0]);
    float u1 = __cosf(x.y + w[1]);
    float u2 = __cosf(x.z + w[2]);
    float u3 = __cosf(x.w + w[3]);
    float4 r;
    r.y = u0 * u1;
    r.z = r.y * u2;
    r.w = r.z * u3;
    r.x = u1 * u2 * u3;
    return r;
}

__device__ __forceinline__ unsigned packh2(float lo, float hi) {
    __half2 h = __floats2half2_rn(lo, hi);
    return *reinterpret_cast<unsigned*>(&h);
}

// Role-split QKV: blocks 0-255 -> Q frags, 256-511 -> K frags, 512-767 -> V' frags.
__global__ void __launch_bounds__(256) qkv_kernel(
    const float* __restrict__ x,
    const float* __restrict__ wQ,
    const float* __restrict__ wK,
    const float* __restrict__ wV)
{
    unsigned t = blockIdx.x * 256 + threadIdx.x;
    unsigned role = t >> 16;
    unsigned n = t & (NROWS - 1);
    int b = n >> 11, kl = n & 2047;
    float4 xv = reinterpret_cast<const float4*>(x)[n];

    if (role == 0) {
        // Q: A-fragment (m16n8k8 row-major). row r within 16-query group qg.
        const float ALPHA = 0.72134752044448170367f;  // 0.5 * log2(e)
        float4 q = circuit4(xv, wQ);
        int qg = kl >> 4, r = kl & 15;
        int j = r >> 3, rb = r & 7;
        unsigned base = (((b * 128 + qg) * 32) + rb * 4) * 2 + j;
        g_qf[base]     = packh2(q.x * ALPHA, q.y * ALPHA);
        g_qf[base + 2] = packh2(q.z * ALPHA, q.w * ALPHA);
        g_qf[base + 4] = 0;
        g_qf[base + 6] = 0;
    } else if (role == 1) {
        // K: B-fragment (col-major). key slot s -> column s -> lanes s*4+{0..3}.
        float4 k = circuit4(xv, wK);
        int g = kl >> 3, s = kl & 7;
        int g4 = g >> 2, j = g & 3;
        unsigned base = ((((b * 64 + g4) * 32) + s * 4) * 4) + j;
        g_kf[base]      = packh2(k.x, k.y);
        g_kf[base + 4]  = packh2(k.z, k.w);
        g_kf[base + 8]  = 0;
        g_kf[base + 12] = 0;
    } else {
        // V': B-fragment rows=keys, cols={v0..v3, 1, 0,0,0}.
        // word(lane=c*4+sp, j) = half2(val_c[key 2sp], val_c[key 2sp+1]).
        float4 v = circuit4(xv, wV);
        float vals[8] = {v.x, v.y, v.z, v.w, 1.0f, 0.f, 0.f, 0.f};
        float pv[8];
        #pragma unroll
        for (int c = 0; c < 8; c++)
            pv[c] = __shfl_xor_sync(0xFFFFFFFFu, vals[c], 1);
        if ((kl & 1) == 0) {
            int g = kl >> 3, s = kl & 7;
            int g4 = g >> 2, j = g & 3, sp = s >> 1;
            unsigned rowbase = (b * 64 + g4) * 32;
            #pragma unroll
            for (int c = 0; c < 8; c++)
                g_vf[(rowbase + c * 4 + sp) * 4 + j] = packh2(vals[c], pv[c]);
        }
    }
}

// 16-key step: 2x QK m16n8k8 (f16 out) -> ex2 -> 1x PV m16n8k16 (f32 acc).
__device__ __forceinline__ void step16(uint2 aq, unsigned k0, unsigned k1,
                                       unsigned v0, unsigned v1,
                                       float& d0, float& d1, float& d2, float& d3)
{
    unsigned p0, p1, p2, p3;
    asm("mma.sync.aligned.m16n8k8.row.col.f16.f16.f16.f16 "
        "{%0,%1}, {%2,%3}, {%4}, {%5,%6};"
        : "=r"(p0), "=r"(p1)
        : "r"(aq.x), "r"(aq.y), "r"(k0), "r"(0u), "r"(0u));
    asm("mma.sync.aligned.m16n8k8.row.col.f16.f16.f16.f16 "
        "{%0,%1}, {%2,%3}, {%4}, {%5,%6};"
        : "=r"(p2), "=r"(p3)
        : "r"(aq.x), "r"(aq.y), "r"(k1), "r"(0u), "r"(0u));
    asm("ex2.approx.f16x2 %0, %0;" : "+r"(p0));
    asm("ex2.approx.f16x2 %0, %0;" : "+r"(p1));
    asm("ex2.approx.f16x2 %0, %0;" : "+r"(p2));
    asm("ex2.approx.f16x2 %0, %0;" : "+r"(p3));
    asm("mma.sync.aligned.m16n8k16.row.col.f32.f16.f16.f32 "
        "{%0,%1,%2,%3}, {%4,%5,%6,%7}, {%8,%9}, {%0,%1,%2,%3};"
        : "+f"(d0), "+f"(d1), "+f"(d2), "+f"(d3)
        : "r"(p0), "r"(p1), "r"(p2), "r"(p3), "r"(v0), "r"(v1));
}

__global__ void __launch_bounds__(256) attn_kernel()
{
    __shared__ uint4 sK[CHUNK_G4 * 32];   // 8 KB
    __shared__ uint4 sV[CHUNK_G4 * 32];   // 8 KB
    __shared__ float epi[8][16][6];

    int b = blockIdx.y;
    int split = blockIdx.z;
    int w = threadIdx.x >> 5, lane = threadIdx.x & 31;
    int qg = blockIdx.x * 8 + w;

    uint2 aq = reinterpret_cast<const uint2*>(g_qf)[(b * 128 + qg) * 32 + lane];

    float d0 = 0.f, d1 = 0.f, d2 = 0.f, d3 = 0.f;

    for (int c = 0; c < 2; c++) {   // 2 chunks of 512 keys per split
        int g4base = (b * 64) + split * 32 + c * CHUNK_G4;
        __syncthreads();
        const uint4* gk = reinterpret_cast<const uint4*>(g_kf) + g4base * 32;
        const uint4* gv = reinterpret_cast<const uint4*>(g_vf) + g4base * 32;
        sK[threadIdx.x]       = gk[threadIdx.x];
        sK[threadIdx.x + 256] = gk[threadIdx.x + 256];
        sV[threadIdx.x]       = gv[threadIdx.x];
        sV[threadIdx.x + 256] = gv[threadIdx.x + 256];
        __syncthreads();
        #pragma unroll 4
        for (int g4 = 0; g4 < CHUNK_G4; g4++) {
            uint4 kk = sK[g4 * 32 + lane];
            uint4 vv = sV[g4 * 32 + lane];
            step16(aq, kk.x, kk.y, vv.x, vv.y, d0, d1, d2, d3);
            step16(aq, kk.z, kk.w, vv.z, vv.w, d0, d1, d2, d3);
        }
    }

    // Epilogue: PV C cols per lane%4: 0->(v0,v1) 1->(v2,v3) 2->(den,0) 3->(0,0)
    int r = lane >> 2, q4 = lane & 3;
    if (q4 == 0) {
        epi[w][r][0] = d0; epi[w][r][1] = d1;
        epi[w][r + 8][0] = d2; epi[w][r + 8][1] = d3;
    } else if (q4 == 1) {
        epi[w][r][2] = d0; epi[w][r][3] = d1;
        epi[w][r + 8][2] = d2; epi[w][r + 8][3] = d3;
    } else if (q4 == 2) {
        epi[w][r][4] = d0;
        epi[w][r + 8][4] = d2;
    }
    __syncwarp();
    if (lane < 16) {
        int n = b * NS + qg * 16 + lane;
        g_pv[split * NROWS + n] = make_float4(epi[w][lane][0], epi[w][lane][1],
                                              epi[w][lane][2], epi[w][lane][3]);
        g_pd[split * NROWS + n] = epi[w][lane][4];
    }
}

__global__ void __launch_bounds__(256) combine_kernel(
    const float* __restrict__ wC, float* __restrict__ out)
{
    int n = blockIdx.x * 256 + threadIdx.x;
    float4 a = g_pv[n];
    float4 c = g_pv[NROWS + n];
    float den = g_pd[n] + g_pd[NROWS + n];
    float inv = 1.0f / den;
    float4 ctx = make_float4((a.x + c.x) * inv, (a.y + c.y) * inv,
                             (a.z + c.z) * inv, (a.w + c.w) * inv);
    reinterpret_cast<float4*>(out)[n] = circuit4(ctx, wC);
}

extern "C" void kernel_launch(void* const* d_in, const int* in_sizes, int n_in,
                              void* d_out, int out_size)
{
    const float* x  = (const float*)d_in[0];
    const float* wQ = (const float*)d_in[1];
    const float* wK = (const float*)d_in[2];
    const float* wV = (const float*)d_in[3];
    const float* wC = (const float*)d_in[4];
    float* out = (float*)d_out;

    qkv_kernel<<<3 * NROWS / 256, 256>>>(x, wQ, wK, wV);
    attn_kernel<<<dim3(16, NB, KSPLIT), 256>>>();
    combine_kernel<<<NROWS / 256, 256>>>(wC, out);
}